// round 1
// baseline (speedup 1.0000x reference)
#include <cuda_runtime.h>
#include <math.h>

#define N_TOK 4096      // B*T
#define DDIM  1024
#define HDIM  4096
#define NEXP  8
#define NSLOT (N_TOK * 2)

// ---------------- scratch (static device globals; no cudaMalloc) ----------
__device__ float g_h[(size_t)NSLOT * HDIM];   // 128 MB: gelu(x@W1+b1) per slot
__device__ float g_eo[(size_t)NSLOT * DDIM];  //  32 MB: expert output per slot
__device__ int   g_perm[NSLOT];               // slot -> token
__device__ int   g_slot_of[NSLOT];            // (token,k) -> slot
__device__ int   g_tope[NSLOT];               // (token,k) -> expert
__device__ float g_topw[NSLOT];               // (token,k) -> gate weight
__device__ int   g_cnt[NEXP];
__device__ int   g_off[NEXP];
__device__ int   g_cur[NEXP];

// ---------------- kernel 0: reset counters --------------------------------
__global__ void reset_kernel() {
    int i = threadIdx.x;
    if (i < NEXP) { g_cnt[i] = 0; g_cur[i] = 0; }
}

// ---------------- kernel 1: gating (1 warp per token) ----------------------
__global__ void gate_kernel(const float* __restrict__ x,
                            const float* __restrict__ Wg,
                            const float* __restrict__ bg) {
    int t = blockIdx.x;
    int lane = threadIdx.x;
    const float* xr = x + (size_t)t * DDIM;

    float p[NEXP];
#pragma unroll
    for (int e = 0; e < NEXP; e++) p[e] = 0.f;

    for (int d = lane; d < DDIM; d += 32) {
        float xv = xr[d];
        const float4* w4 = reinterpret_cast<const float4*>(Wg + (size_t)d * NEXP);
        float4 a = w4[0], b = w4[1];
        p[0] += xv * a.x; p[1] += xv * a.y; p[2] += xv * a.z; p[3] += xv * a.w;
        p[4] += xv * b.x; p[5] += xv * b.y; p[6] += xv * b.z; p[7] += xv * b.w;
    }
#pragma unroll
    for (int off = 16; off; off >>= 1)
#pragma unroll
        for (int e = 0; e < NEXP; e++)
            p[e] += __shfl_xor_sync(0xffffffffu, p[e], off);

    if (lane == 0) {
#pragma unroll
        for (int e = 0; e < NEXP; e++) p[e] += bg[e];
        // top-2 by logit (== top-2 by softmax prob)
        int i0 = 0;
#pragma unroll
        for (int e = 1; e < NEXP; e++) if (p[e] > p[i0]) i0 = e;
        int i1 = (i0 == 0) ? 1 : 0;
#pragma unroll
        for (int e = 0; e < NEXP; e++)
            if (e != i0 && p[e] > p[i1]) i1 = e;
        // normalized top-2 gate weights: softmax ratio among the two
        float e1 = expf(p[i1] - p[i0]);      // <= 1
        float w0 = 1.0f / (1.0f + e1);
        float w1 = e1 / (1.0f + e1);
        g_tope[t * 2 + 0] = i0;  g_tope[t * 2 + 1] = i1;
        g_topw[t * 2 + 0] = w0;  g_topw[t * 2 + 1] = w1;
        atomicAdd(&g_cnt[i0], 1);
        atomicAdd(&g_cnt[i1], 1);
    }
}

// ---------------- kernel 2: expert offsets (serial, tiny) ------------------
__global__ void offsets_kernel() {
    if (threadIdx.x == 0) {
        int acc = 0;
        for (int e = 0; e < NEXP; e++) { g_off[e] = acc; acc += g_cnt[e]; }
    }
}

// ---------------- kernel 3: scatter tokens into expert-sorted slots --------
__global__ void scatter_kernel() {
    int t = blockIdx.x * blockDim.x + threadIdx.x;
    if (t >= N_TOK) return;
#pragma unroll
    for (int k = 0; k < 2; k++) {
        int e = g_tope[t * 2 + k];
        int pos = g_off[e] + atomicAdd(&g_cur[e], 1);
        g_perm[pos] = t;
        g_slot_of[t * 2 + k] = pos;
    }
}

// ---------------- GEMM1: h[slot] = gelu(x[tok] @ W1[e] + b1[e]) ------------
// 128x128x16 tile, 256 threads, 8x8 micro-tile
__global__ __launch_bounds__(256) void gemm1_kernel(
    const float* __restrict__ x, const float* __restrict__ W1,
    const float* __restrict__ b1) {
    int e = blockIdx.z;
    int cnt = g_cnt[e];
    int m0 = blockIdx.x * 128;
    if (m0 >= cnt) return;
    int off = g_off[e];
    int n0 = blockIdx.y * 128;
    const float* Bptr = W1 + (size_t)e * DDIM * HDIM;   // [D][H]

    __shared__ float As[16][136];
    __shared__ float Bs[16][128];
    __shared__ int rowtok[128];

    int tid = threadIdx.x;
    if (tid < 128) {
        int r = m0 + tid;
        rowtok[tid] = (r < cnt) ? g_perm[off + r] : -1;
    }
    __syncthreads();

    float acc[8][8];
#pragma unroll
    for (int i = 0; i < 8; i++)
#pragma unroll
        for (int j = 0; j < 8; j++) acc[i][j] = 0.f;

    int tm = (tid / 16) * 8;
    int tn = (tid % 16) * 8;

    for (int k0 = 0; k0 < DDIM; k0 += 16) {
#pragma unroll
        for (int f = 0; f < 2; f++) {                 // A tile (gathered rows)
            int id = tid + f * 256;                   // 0..511
            int row = id >> 2;                        // 0..127
            int k4 = (id & 3) * 4;
            int tok = rowtok[row];
            float4 v = make_float4(0.f, 0.f, 0.f, 0.f);
            if (tok >= 0)
                v = *reinterpret_cast<const float4*>(&x[(size_t)tok * DDIM + k0 + k4]);
            As[k4 + 0][row] = v.x; As[k4 + 1][row] = v.y;
            As[k4 + 2][row] = v.z; As[k4 + 3][row] = v.w;
        }
#pragma unroll
        for (int f = 0; f < 2; f++) {                 // B tile
            int id = tid + f * 256;
            int k = id >> 5;                          // 0..15
            int n4 = (id & 31) * 4;
            *reinterpret_cast<float4*>(&Bs[k][n4]) =
                *reinterpret_cast<const float4*>(&Bptr[(size_t)(k0 + k) * HDIM + n0 + n4]);
        }
        __syncthreads();
#pragma unroll
        for (int k = 0; k < 16; k++) {
            float a[8], b[8];
            const float4* ap = reinterpret_cast<const float4*>(&As[k][tm]);
            float4 a0 = ap[0], a1 = ap[1];
            a[0]=a0.x; a[1]=a0.y; a[2]=a0.z; a[3]=a0.w;
            a[4]=a1.x; a[5]=a1.y; a[6]=a1.z; a[7]=a1.w;
            const float4* bp = reinterpret_cast<const float4*>(&Bs[k][tn]);
            float4 b0 = bp[0], b1v = bp[1];
            b[0]=b0.x; b[1]=b0.y; b[2]=b0.z; b[3]=b0.w;
            b[4]=b1v.x; b[5]=b1v.y; b[6]=b1v.z; b[7]=b1v.w;
#pragma unroll
            for (int i = 0; i < 8; i++)
#pragma unroll
                for (int j = 0; j < 8; j++) acc[i][j] += a[i] * b[j];
        }
        __syncthreads();
    }

#pragma unroll
    for (int i = 0; i < 8; i++) {
        int r = m0 + tm + i;
        if (r >= cnt) continue;
        int slot = off + r;
        float* hp = g_h + (size_t)slot * HDIM + n0 + tn;
#pragma unroll
        for (int j = 0; j < 8; j++) {
            float v = acc[i][j] + b1[(size_t)e * HDIM + n0 + tn + j];
            hp[j] = v * normcdff(v);   // exact gelu: x * Phi(x)
        }
    }
}

// ---------------- GEMM2: eo[slot] = h[slot] @ W2[e] + b2[e] ----------------
__global__ __launch_bounds__(256) void gemm2_kernel(
    const float* __restrict__ W2, const float* __restrict__ b2) {
    int e = blockIdx.z;
    int cnt = g_cnt[e];
    int m0 = blockIdx.x * 128;
    if (m0 >= cnt) return;
    int off = g_off[e];
    int n0 = blockIdx.y * 128;
    const float* Bptr = W2 + (size_t)e * HDIM * DDIM;   // [H][D]

    __shared__ float As[16][136];
    __shared__ float Bs[16][128];

    int tid = threadIdx.x;
    float acc[8][8];
#pragma unroll
    for (int i = 0; i < 8; i++)
#pragma unroll
        for (int j = 0; j < 8; j++) acc[i][j] = 0.f;

    int tm = (tid / 16) * 8;
    int tn = (tid % 16) * 8;

    for (int k0 = 0; k0 < HDIM; k0 += 16) {
#pragma unroll
        for (int f = 0; f < 2; f++) {                 // A tile (contiguous slots)
            int id = tid + f * 256;
            int row = id >> 2;
            int k4 = (id & 3) * 4;
            float4 v = make_float4(0.f, 0.f, 0.f, 0.f);
            if (m0 + row < cnt)
                v = *reinterpret_cast<const float4*>(
                        &g_h[(size_t)(off + m0 + row) * HDIM + k0 + k4]);
            As[k4 + 0][row] = v.x; As[k4 + 1][row] = v.y;
            As[k4 + 2][row] = v.z; As[k4 + 3][row] = v.w;
        }
#pragma unroll
        for (int f = 0; f < 2; f++) {                 // B tile
            int id = tid + f * 256;
            int k = id >> 5;
            int n4 = (id & 31) * 4;
            *reinterpret_cast<float4*>(&Bs[k][n4]) =
                *reinterpret_cast<const float4*>(&Bptr[(size_t)(k0 + k) * DDIM + n0 + n4]);
        }
        __syncthreads();
#pragma unroll
        for (int k = 0; k < 16; k++) {
            float a[8], b[8];
            const float4* ap = reinterpret_cast<const float4*>(&As[k][tm]);
            float4 a0 = ap[0], a1 = ap[1];
            a[0]=a0.x; a[1]=a0.y; a[2]=a0.z; a[3]=a0.w;
            a[4]=a1.x; a[5]=a1.y; a[6]=a1.z; a[7]=a1.w;
            const float4* bp = reinterpret_cast<const float4*>(&Bs[k][tn]);
            float4 b0 = bp[0], b1v = bp[1];
            b[0]=b0.x; b[1]=b0.y; b[2]=b0.z; b[3]=b0.w;
            b[4]=b1v.x; b[5]=b1v.y; b[6]=b1v.z; b[7]=b1v.w;
#pragma unroll
            for (int i = 0; i < 8; i++)
#pragma unroll
                for (int j = 0; j < 8; j++) acc[i][j] += a[i] * b[j];
        }
        __syncthreads();
    }

#pragma unroll
    for (int i = 0; i < 8; i++) {
        int r = m0 + tm + i;
        if (r >= cnt) continue;
        int slot = off + r;
        float* op = g_eo + (size_t)slot * DDIM + n0 + tn;
#pragma unroll
        for (int j = 0; j < 8; j++)
            op[j] = acc[i][j] + b2[(size_t)e * DDIM + n0 + tn + j];
    }
}

// ---------------- combine: out[t] = w0*eo[s0] + w1*eo[s1] ------------------
__global__ void combine_kernel(float* __restrict__ out) {
    int t = blockIdx.x;
    int s0 = g_slot_of[t * 2 + 0], s1 = g_slot_of[t * 2 + 1];
    float w0 = g_topw[t * 2 + 0], w1 = g_topw[t * 2 + 1];
    const float4* a = reinterpret_cast<const float4*>(g_eo + (size_t)s0 * DDIM);
    const float4* b = reinterpret_cast<const float4*>(g_eo + (size_t)s1 * DDIM);
    float4* o = reinterpret_cast<float4*>(out + (size_t)t * DDIM);
    for (int i = threadIdx.x; i < DDIM / 4; i += blockDim.x) {
        float4 va = a[i], vb = b[i];
        o[i] = make_float4(w0 * va.x + w1 * vb.x,
                           w0 * va.y + w1 * vb.y,
                           w0 * va.z + w1 * vb.z,
                           w0 * va.w + w1 * vb.w);
    }
}

// ---------------- launch ----------------------------------------------------
extern "C" void kernel_launch(void* const* d_in, const int* in_sizes, int n_in,
                              void* d_out, int out_size) {
    const float* x  = (const float*)d_in[0];
    const float* Wg = (const float*)d_in[1];
    const float* bg = (const float*)d_in[2];
    const float* W1 = (const float*)d_in[3];
    const float* b1 = (const float*)d_in[4];
    const float* W2 = (const float*)d_in[5];
    const float* b2 = (const float*)d_in[6];
    float* out = (float*)d_out;

    reset_kernel<<<1, 32>>>();
    gate_kernel<<<N_TOK, 32>>>(x, Wg, bg);
    offsets_kernel<<<1, 32>>>();
    scatter_kernel<<<(N_TOK + 255) / 256, 256>>>();
    gemm1_kernel<<<dim3(N_TOK / 128, HDIM / 128, NEXP), 256>>>(x, W1, b1);
    gemm2_kernel<<<dim3(N_TOK / 128, DDIM / 128, NEXP), 256>>>(W2, b2);
    combine_kernel<<<N_TOK, 256>>>(out);
}

// round 3
// speedup vs baseline: 2.9722x; 2.9722x over previous
#include <cuda_runtime.h>
#include <math.h>
#include <stdint.h>

#define N_TOK 4096      // B*T
#define DDIM  1024
#define HDIM  4096
#define NEXP  8
#define NSLOT (N_TOK * 2)

// ---------------- scratch (static device globals; no cudaMalloc) ----------
__device__ float g_h[(size_t)NSLOT * HDIM];          // 128 MB
__device__ float g_eo[(size_t)NSLOT * DDIM];         //  32 MB
__device__ int   g_perm[NSLOT];
__device__ int   g_slot_of[NSLOT];
__device__ int   g_tope[NSLOT];
__device__ float g_topw[NSLOT];
__device__ int   g_cnt[NEXP];
__device__ int   g_off[NEXP];
__device__ int   g_cur[NEXP];

// ======================= PTX helpers (compute_103-safe) ====================
__device__ __forceinline__ uint32_t smem_u32(const void* p) {
    uint32_t a;
    asm("{ .reg .u64 t; cvta.to.shared.u64 t, %1; cvt.u32.u64 %0, t; }"
        : "=r"(a) : "l"(p));
    return a;
}
__device__ __forceinline__ void cp_async16(uint32_t dst, const void* src, uint32_t sz) {
    asm volatile("cp.async.ca.shared.global [%0], [%1], 16, %2;"
                 :: "r"(dst), "l"(src), "r"(sz) : "memory");
}
#define CP_COMMIT() asm volatile("cp.async.commit_group;" ::: "memory")
#define CP_WAIT(n)  asm volatile("cp.async.wait_group %0;" :: "n"(n) : "memory")

__device__ __forceinline__ void ldsm_x4(uint32_t* r, uint32_t addr) {
    asm volatile("ldmatrix.sync.aligned.m8n8.x4.shared.b16 {%0,%1,%2,%3}, [%4];"
                 : "=r"(r[0]), "=r"(r[1]), "=r"(r[2]), "=r"(r[3]) : "r"(addr));
}
__device__ __forceinline__ uint32_t to_tf32(uint32_t bits) {
    uint32_t o;
    asm("cvt.rna.tf32.f32 %0, %1;" : "=r"(o) : "f"(__uint_as_float(bits)));
    return o;
}
__device__ __forceinline__ void mma_tf32(float* d, const uint32_t* a, const uint32_t* b) {
    asm volatile(
        "mma.sync.aligned.m16n8k8.row.col.f32.tf32.tf32.f32 "
        "{%0,%1,%2,%3}, {%4,%5,%6,%7}, {%8,%9}, {%0,%1,%2,%3};"
        : "+f"(d[0]), "+f"(d[1]), "+f"(d[2]), "+f"(d[3])
        : "r"(a[0]), "r"(a[1]), "r"(a[2]), "r"(a[3]), "r"(b[0]), "r"(b[1]));
}

// ======================= small kernels ======================================
__global__ void reset_kernel() {
    int i = threadIdx.x;
    if (i < NEXP) { g_cnt[i] = 0; g_cur[i] = 0; }
}

__global__ void gate_kernel(const float* __restrict__ x,
                            const float* __restrict__ Wg,
                            const float* __restrict__ bg) {
    int t = blockIdx.x;
    int lane = threadIdx.x;
    const float* xr = x + (size_t)t * DDIM;
    float p[NEXP];
#pragma unroll
    for (int e = 0; e < NEXP; e++) p[e] = 0.f;
    for (int d = lane; d < DDIM; d += 32) {
        float xv = xr[d];
        const float4* w4 = reinterpret_cast<const float4*>(Wg + (size_t)d * NEXP);
        float4 a = w4[0], b = w4[1];
        p[0] += xv * a.x; p[1] += xv * a.y; p[2] += xv * a.z; p[3] += xv * a.w;
        p[4] += xv * b.x; p[5] += xv * b.y; p[6] += xv * b.z; p[7] += xv * b.w;
    }
#pragma unroll
    for (int off = 16; off; off >>= 1)
#pragma unroll
        for (int e = 0; e < NEXP; e++)
            p[e] += __shfl_xor_sync(0xffffffffu, p[e], off);
    if (lane == 0) {
#pragma unroll
        for (int e = 0; e < NEXP; e++) p[e] += bg[e];
        int i0 = 0;
#pragma unroll
        for (int e = 1; e < NEXP; e++) if (p[e] > p[i0]) i0 = e;
        int i1 = (i0 == 0) ? 1 : 0;
#pragma unroll
        for (int e = 0; e < NEXP; e++)
            if (e != i0 && p[e] > p[i1]) i1 = e;
        float e1 = expf(p[i1] - p[i0]);
        float w0 = 1.0f / (1.0f + e1);
        float w1 = e1 / (1.0f + e1);
        g_tope[t * 2 + 0] = i0;  g_tope[t * 2 + 1] = i1;
        g_topw[t * 2 + 0] = w0;  g_topw[t * 2 + 1] = w1;
        atomicAdd(&g_cnt[i0], 1);
        atomicAdd(&g_cnt[i1], 1);
    }
}

__global__ void offsets_kernel() {
    if (threadIdx.x == 0) {
        int acc = 0;
        for (int e = 0; e < NEXP; e++) { g_off[e] = acc; acc += g_cnt[e]; }
    }
}

__global__ void scatter_kernel() {
    int t = blockIdx.x * blockDim.x + threadIdx.x;
    if (t >= N_TOK) return;
#pragma unroll
    for (int k = 0; k < 2; k++) {
        int e = g_tope[t * 2 + k];
        int pos = g_off[e] + atomicAdd(&g_cur[e], 1);
        g_perm[pos] = t;
        g_slot_of[t * 2 + k] = pos;
    }
}

// ======================= tf32 mma.sync grouped GEMM =========================
// CTA tile 128(M) x 256(N), k-chunk 32, 8 warps (2m x 4n), warp tile 64x64.
// A smem: [128 m][32 k] fp32, 128B rows, 16B-granule XOR swizzle (ldmatrix).
// B smem: [32 k][264 n] fp32 (8-float pad -> conflict-free LDS fragments).
// Double-buffered, cp.async fed.
#define ABUF_B   16384
#define BBUF_B   33792
#define OFF_A    1024
#define OFF_B    (OFF_A + 2 * ABUF_B)             // 33792
#define SM_BYTES (OFF_B + 2 * BBUF_B)             // 101376

template <int KDIM, bool GATHER, bool DOGELU>
__global__ __launch_bounds__(256, 1) void moe_gemm(
    const float* __restrict__ Asrc, const float* __restrict__ Bg,
    const float* __restrict__ bias, float* __restrict__ Out, int Ntot) {
    extern __shared__ char smem[];
    const int e = blockIdx.z;
    const int cnt = g_cnt[e];
    const int m0 = blockIdx.x * 128;
    if (m0 >= cnt) return;
    const int off = g_off[e];
    const int n0 = blockIdx.y * 256;
    const float* Bte = Bg + (size_t)e * KDIM * Ntot;   // [K][Ntot]

    const uint32_t sb = smem_u32(smem);
    const int tid = threadIdx.x;
    const int wid = tid >> 5, lane = tid & 31;
    const int wm = wid & 1, wn = wid >> 1;
    const int m_base = wm * 64, n_base = wn * 64;

    int* rowtok = (int*)smem;
    if (GATHER && tid < 128) {
        int r = m0 + tid;
        rowtok[tid] = (r < cnt) ? g_perm[off + r] : -1;
    }
    __syncthreads();

    constexpr int NC = KDIM / 32;

    // ---- chunk loader ----
    auto load_chunk = [&](int c) {
        const int k0 = c * 32;
        const uint32_t Abs = sb + OFF_A + (c & 1) * ABUF_B;
        const uint32_t Bbs = sb + OFF_B + (c & 1) * BBUF_B;
        // A: 128 rows x 32 floats = 1024 granules of 16B
#pragma unroll
        for (int f = 0; f < 4; f++) {
            int id = tid + f * 256;
            int row = id >> 3, g = id & 7;
            uint32_t sz = 16;
            const char* src;
            if (GATHER) {
                int tok = rowtok[row];
                if (tok < 0) { sz = 0; tok = 0; }
                src = (const char*)(Asrc + (size_t)tok * KDIM + k0) + g * 16;
            } else {
                int mr = m0 + row;
                if (mr >= cnt) { sz = 0; mr = 0; }
                src = (const char*)(Asrc + (size_t)(off + mr) * KDIM + k0) + g * 16;
            }
            cp_async16(Abs + row * 128 + ((g ^ (row & 7)) << 4), src, sz);
        }
        // B: 32 rows x 256 floats = 2048 granules
#pragma unroll
        for (int f = 0; f < 8; f++) {
            int id = tid + f * 256;
            int kr = id >> 6, g = id & 63;
            const char* src =
                (const char*)(Bte + (size_t)(k0 + kr) * Ntot + n0) + g * 16;
            cp_async16(Bbs + kr * 1056 + g * 16, src, 16);
        }
        CP_COMMIT();
    };

    float acc[4][8][4];
#pragma unroll
    for (int mi = 0; mi < 4; mi++)
#pragma unroll
        for (int ni = 0; ni < 8; ni++)
#pragma unroll
            for (int q = 0; q < 4; q++) acc[mi][ni][q] = 0.f;

    load_chunk(0);

    const int a_rowsel = ((lane >> 3) & 1) * 8 + (lane & 7);
    const int a_gsel = (lane >> 4);

#pragma unroll 1
    for (int c = 0; c < NC; c++) {
        if (c + 1 < NC) { load_chunk(c + 1); CP_WAIT(1); }
        else            { CP_WAIT(0); }
        __syncthreads();
        const uint32_t Abs = sb + OFF_A + (c & 1) * ABUF_B;
        const float* Bsf = (const float*)(smem + OFF_B + (c & 1) * BBUF_B);
#pragma unroll
        for (int ks = 0; ks < 4; ks++) {
            uint32_t a[4][4];
#pragma unroll
            for (int mi = 0; mi < 4; mi++) {
                int row = m_base + mi * 16 + a_rowsel;
                int g = ks * 2 + a_gsel;
                ldsm_x4(a[mi], Abs + row * 128 + ((g ^ (row & 7)) << 4));
#pragma unroll
                for (int q = 0; q < 4; q++) a[mi][q] = to_tf32(a[mi][q]);
            }
            uint32_t b[8][2];
            const int kr = ks * 8 + (lane & 3);
            const int nb = n_base + (lane >> 2);
#pragma unroll
            for (int ni = 0; ni < 8; ni++) {
                int w = kr * 264 + nb + ni * 8;
                b[ni][0] = to_tf32(__float_as_uint(Bsf[w]));
                b[ni][1] = to_tf32(__float_as_uint(Bsf[w + 4 * 264]));
            }
#pragma unroll
            for (int mi = 0; mi < 4; mi++)
#pragma unroll
                for (int ni = 0; ni < 8; ni++)
                    mma_tf32(acc[mi][ni], a[mi], b[ni]);
        }
        __syncthreads();
    }

    // ---- epilogue: bias (+gelu) + store ----
    const int lr = lane >> 2;          // 0..7
    const int lc = (lane & 3) * 2;     // 0,2,4,6
    float2 bv[8];
#pragma unroll
    for (int ni = 0; ni < 8; ni++) {
        int col = n0 + n_base + ni * 8 + lc;
        const float* bp = bias + (size_t)e * Ntot + col;
        bv[ni] = make_float2(bp[0], bp[1]);
    }
#pragma unroll
    for (int mi = 0; mi < 4; mi++) {
        int r0 = m0 + m_base + mi * 16 + lr;
        int r1 = r0 + 8;
        bool v0 = r0 < cnt, v1 = r1 < cnt;
        float* o0 = Out + (size_t)(off + r0) * Ntot + n0 + n_base + lc;
        float* o1 = Out + (size_t)(off + r1) * Ntot + n0 + n_base + lc;
#pragma unroll
        for (int ni = 0; ni < 8; ni++) {
            if (v0) {
                float x0 = acc[mi][ni][0] + bv[ni].x;
                float x1 = acc[mi][ni][1] + bv[ni].y;
                if (DOGELU) { x0 = x0 * normcdff(x0); x1 = x1 * normcdff(x1); }
                *reinterpret_cast<float2*>(o0 + ni * 8) = make_float2(x0, x1);
            }
            if (v1) {
                float x2 = acc[mi][ni][2] + bv[ni].x;
                float x3 = acc[mi][ni][3] + bv[ni].y;
                if (DOGELU) { x2 = x2 * normcdff(x2); x3 = x3 * normcdff(x3); }
                *reinterpret_cast<float2*>(o1 + ni * 8) = make_float2(x2, x3);
            }
        }
    }
}

// ---------------- combine: out[t] = w0*eo[s0] + w1*eo[s1] ------------------
__global__ void combine_kernel(float* __restrict__ out) {
    int t = blockIdx.x;
    int s0 = g_slot_of[t * 2 + 0], s1 = g_slot_of[t * 2 + 1];
    float w0 = g_topw[t * 2 + 0], w1 = g_topw[t * 2 + 1];
    const float4* a = reinterpret_cast<const float4*>(g_eo + (size_t)s0 * DDIM);
    const float4* b = reinterpret_cast<const float4*>(g_eo + (size_t)s1 * DDIM);
    float4* o = reinterpret_cast<float4*>(out + (size_t)t * DDIM);
    for (int i = threadIdx.x; i < DDIM / 4; i += blockDim.x) {
        float4 va = a[i], vb = b[i];
        o[i] = make_float4(w0 * va.x + w1 * vb.x, w0 * va.y + w1 * vb.y,
                           w0 * va.z + w1 * vb.z, w0 * va.w + w1 * vb.w);
    }
}

// ---------------- launch ----------------------------------------------------
extern "C" void kernel_launch(void* const* d_in, const int* in_sizes, int n_in,
                              void* d_out, int out_size) {
    const float* x  = (const float*)d_in[0];
    const float* Wg = (const float*)d_in[1];
    const float* bg = (const float*)d_in[2];
    const float* W1 = (const float*)d_in[3];
    const float* b1 = (const float*)d_in[4];
    const float* W2 = (const float*)d_in[5];
    const float* b2 = (const float*)d_in[6];
    float* out = (float*)d_out;

    void *p_h, *p_eo;
    cudaGetSymbolAddress(&p_h,  g_h);
    cudaGetSymbolAddress(&p_eo, g_eo);

    cudaFuncSetAttribute(moe_gemm<DDIM, true,  true>,
                         cudaFuncAttributeMaxDynamicSharedMemorySize, SM_BYTES);
    cudaFuncSetAttribute(moe_gemm<HDIM, false, false>,
                         cudaFuncAttributeMaxDynamicSharedMemorySize, SM_BYTES);

    reset_kernel<<<1, 32>>>();
    gate_kernel<<<N_TOK, 32>>>(x, Wg, bg);
    offsets_kernel<<<1, 32>>>();
    scatter_kernel<<<(N_TOK + 255) / 256, 256>>>();
    // GEMM1: h = gelu(x[perm] @ W1 + b1)   K=1024, N=4096
    moe_gemm<DDIM, true, true><<<dim3(32, HDIM / 256, NEXP), 256, SM_BYTES>>>(
        x, W1, b1, (float*)p_h, HDIM);
    // GEMM2: eo = h @ W2 + b2              K=4096, N=1024
    moe_gemm<HDIM, false, false><<<dim3(32, DDIM / 256, NEXP), 256, SM_BYTES>>>(
        (const float*)p_h, W2, b2, (float*)p_eo, DDIM);
    combine_kernel<<<N_TOK, 256>>>(out);
}